// round 3
// baseline (speedup 1.0000x reference)
#include <cuda_runtime.h>
#include <math.h>

#define BATCH   16384
#define ENCD    512
#define HD      256
#define GD      1024
#define TSTEPS  64
#define ROWS    32
#define NTHR    512
#define KT      16
#define NTILE   (HD / KT)   // 16
#define KT0     32

// v[j] = W_emb @ W_k[:,j] ; u[j] = b_emb @ W_k[:,j] + b_lstm[j]
__device__ float g_v[GD];
__device__ float g_u[GD];

__global__ void precompute_vu_kernel(const float* __restrict__ W_emb,
                                     const float* __restrict__ b_emb,
                                     const float* __restrict__ W_k,
                                     const float* __restrict__ b_lstm) {
    int j = blockIdx.x * blockDim.x + threadIdx.x;
    if (j < GD) {
        float v = 0.f, u = 0.f;
        #pragma unroll
        for (int d = 0; d < 32; ++d) {
            float wk = W_k[d * GD + j];
            v += W_emb[d] * wk;
            u += b_emb[d] * wk;
        }
        g_v[j] = v;
        g_u[j] = u + b_lstm[j];
    }
}

__device__ __forceinline__ float sigmoidf_(float x) {
    return 1.f / (1.f + __expf(-x));
}

__device__ __forceinline__ void cp16(float* dst, const float* src) {
    unsigned s = (unsigned)__cvta_generic_to_shared(dst);
    asm volatile("cp.async.cg.shared.global [%0], [%1], 16;" :: "r"(s), "l"(src));
}

// One CTA owns ROWS=32 batch rows for the whole T=64 recurrence.
// Warp w owns rows 2w,2w+1 completely (lane l -> cols 8l..8l+7, all 4 gates).
// h lives in SMEM (cross-warp GEMM input); c, y live in registers.
// W_r streamed L2->SMEM via cp.async, double-buffered KT=16 row tiles.
__global__ void __launch_bounds__(NTHR, 1)
lstm_decode_kernel(const float* __restrict__ enc,
                   const float* __restrict__ finalx,
                   const float* __restrict__ W_enc,
                   const float* __restrict__ b_enc,
                   const float* __restrict__ W_r,
                   const float* __restrict__ W_red,
                   const float* __restrict__ b_red,
                   float* __restrict__ out)
{
    extern __shared__ float smem[];
    float* sh_h    = smem;                    // ROWS*HD  = 8192
    float* sh_w0   = sh_h + ROWS * HD;        // KT*GD    = 16384
    float* sh_w1   = sh_w0 + KT * GD;         // KT*GD    = 16384
    float* sh_enc  = sh_w1 + KT * GD;         // ROWS*KT0 = 1024
    float* sh_v    = sh_enc + ROWS * KT0;     // GD
    float* sh_u    = sh_v + GD;               // GD
    float* sh_wred = sh_u + GD;               // HD

    const int tid = threadIdx.x;
    const int w   = tid >> 5;
    const int l   = tid & 31;
    const int r0  = 2 * w;
    const int r1  = 2 * w + 1;
    const int nb  = l * 8;                    // this lane's column base
    const int row0 = blockIdx.x * ROWS;

    // ---- setup ----
    for (int i = tid; i < GD; i += NTHR) { sh_v[i] = g_v[i]; sh_u[i] = g_u[i]; }
    for (int i = tid; i < HD; i += NTHR) sh_wred[i] = W_red[i];

    float y0 = finalx[row0 + r0];   // step-0 gates use finalx directly (x0@W_k = finalx*v + u)
    float y1 = finalx[row0 + r1];
    float c0r[8], c1r[8];
    #pragma unroll
    for (int j = 0; j < 8; ++j) { c0r[j] = 0.f; c1r[j] = 0.f; }
    const float bred = __ldg(b_red);

    // ---- h0 = enc @ W_enc + b_enc  ([32,512]@[512,256]) ----
    {
        float a0[8], a1[8];
        #pragma unroll
        for (int j = 0; j < 8; ++j) { a0[j] = 0.f; a1[j] = 0.f; }

        for (int k0 = 0; k0 < ENCD; k0 += KT0) {
            __syncthreads();
            if (tid < 256) {  // stage enc chunk [ROWS][KT0]
                int r  = tid >> 3;
                int c4 = (tid & 7) * 4;
                *reinterpret_cast<float4*>(sh_enc + r * KT0 + c4) =
                    *reinterpret_cast<const float4*>(enc + (size_t)(row0 + r) * ENCD + k0 + c4);
            }
            #pragma unroll
            for (int s = 0; s < 4; ++s) {  // stage W_enc chunk [KT0][HD]
                int slot = tid + s * NTHR;     // 0..2047
                int kk = slot >> 6;
                int c4 = (slot & 63) * 4;
                *reinterpret_cast<float4*>(sh_w0 + kk * HD + c4) =
                    *reinterpret_cast<const float4*>(W_enc + (size_t)(k0 + kk) * HD + c4);
            }
            __syncthreads();
            #pragma unroll
            for (int kk = 0; kk < KT0; ++kk) {
                float av0 = sh_enc[r0 * KT0 + kk];
                float av1 = sh_enc[r1 * KT0 + kk];
                float4 b0 = *reinterpret_cast<const float4*>(sh_w0 + kk * HD + nb);
                float4 b1 = *reinterpret_cast<const float4*>(sh_w0 + kk * HD + nb + 4);
                a0[0] += av0 * b0.x; a0[1] += av0 * b0.y; a0[2] += av0 * b0.z; a0[3] += av0 * b0.w;
                a0[4] += av0 * b1.x; a0[5] += av0 * b1.y; a0[6] += av0 * b1.z; a0[7] += av0 * b1.w;
                a1[0] += av1 * b0.x; a1[1] += av1 * b0.y; a1[2] += av1 * b0.z; a1[3] += av1 * b0.w;
                a1[4] += av1 * b1.x; a1[5] += av1 * b1.y; a1[6] += av1 * b1.z; a1[7] += av1 * b1.w;
            }
        }
        __syncthreads();   // all h0 FMA reads of sh_w0 done
        #pragma unroll
        for (int j = 0; j < 8; ++j) {
            float be = __ldg(b_enc + nb + j);
            sh_h[r0 * HD + nb + j] = a0[j] + be;
            sh_h[r1 * HD + nb + j] = a1[j] + be;
        }
    }

    // ---- prefetch W_r tile 0 into sh_w0 ----
    {
        #pragma unroll
        for (int s = 0; s < 8; ++s) {
            int slot = tid + s * NTHR;         // 0..4095
            int kk = slot >> 8;                // 0..15
            int c4 = (slot & 255) * 4;         // 0..1020
            cp16(sh_w0 + kk * GD + c4, W_r + (size_t)kk * GD + c4);
        }
        asm volatile("cp.async.commit_group;");
    }

    // ---- time loop ----
    for (int t = 0; t < TSTEPS; ++t) {
        float acc[2][4][8];
        #pragma unroll
        for (int i = 0; i < 2; ++i)
            #pragma unroll
            for (int g = 0; g < 4; ++g)
                #pragma unroll
                for (int j = 0; j < 8; ++j) acc[i][g][j] = 0.f;

        for (int jt = 0; jt < NTILE; ++jt) {
            // stage next tile (tile jt+1, or tile 0 again for the next step)
            {
                int nxt = (jt + 1) & (NTILE - 1);
                float* dst = ((jt + 1) & 1) ? sh_w1 : sh_w0;
                const float* src = W_r + (size_t)(nxt * KT) * GD;
                #pragma unroll
                for (int s = 0; s < 8; ++s) {
                    int slot = tid + s * NTHR;
                    int kk = slot >> 8;
                    int c4 = (slot & 255) * 4;
                    cp16(dst + kk * GD + c4, src + (size_t)kk * GD + c4);
                }
                asm volatile("cp.async.commit_group;");
            }
            asm volatile("cp.async.wait_group 1;");   // tile jt landed
            __syncthreads();                          // (also publishes sh_h at jt==0)

            const float* buf = (jt & 1) ? sh_w1 : sh_w0;
            #pragma unroll
            for (int kk = 0; kk < KT; ++kk) {
                int k = jt * KT + kk;
                float av0 = sh_h[r0 * HD + k];        // warp-uniform broadcast
                float av1 = sh_h[r1 * HD + k];
                #pragma unroll
                for (int g = 0; g < 4; ++g) {
                    float4 b0 = *reinterpret_cast<const float4*>(buf + kk * GD + g * HD + nb);
                    float4 b1 = *reinterpret_cast<const float4*>(buf + kk * GD + g * HD + nb + 4);
                    acc[0][g][0] += av0 * b0.x; acc[0][g][1] += av0 * b0.y;
                    acc[0][g][2] += av0 * b0.z; acc[0][g][3] += av0 * b0.w;
                    acc[0][g][4] += av0 * b1.x; acc[0][g][5] += av0 * b1.y;
                    acc[0][g][6] += av0 * b1.z; acc[0][g][7] += av0 * b1.w;
                    acc[1][g][0] += av1 * b0.x; acc[1][g][1] += av1 * b0.y;
                    acc[1][g][2] += av1 * b0.z; acc[1][g][3] += av1 * b0.w;
                    acc[1][g][4] += av1 * b1.x; acc[1][g][5] += av1 * b1.y;
                    acc[1][g][6] += av1 * b1.z; acc[1][g][7] += av1 * b1.w;
                }
            }
            __syncthreads();   // buffer free for restaging next iteration
        }

        // ---- fused gates + state update + warp-local y reduction ----
        float dot0 = 0.f, dot1 = 0.f;
        #pragma unroll
        for (int j = 0; j < 8; ++j) {
            int n = nb + j;
            float vi = sh_v[n],          ui = sh_u[n];
            float vf = sh_v[HD + n],     uf = sh_u[HD + n];
            float vc = sh_v[2 * HD + n], uc = sh_u[2 * HD + n];
            float vo = sh_v[3 * HD + n], uo = sh_u[3 * HD + n];
            float wr = sh_wred[n];
            {
                float gi = acc[0][0][j] + y0 * vi + ui;
                float gf = acc[0][1][j] + y0 * vf + uf;
                float gc = acc[0][2][j] + y0 * vc + uc;
                float go = acc[0][3][j] + y0 * vo + uo;
                float cn = sigmoidf_(gf) * c0r[j] + sigmoidf_(gi) * tanhf(gc);
                float hn = sigmoidf_(go) * tanhf(cn);
                c0r[j] = cn;
                sh_h[r0 * HD + n] = hn;
                dot0 += hn * wr;
            }
            {
                float gi = acc[1][0][j] + y1 * vi + ui;
                float gf = acc[1][1][j] + y1 * vf + uf;
                float gc = acc[1][2][j] + y1 * vc + uc;
                float go = acc[1][3][j] + y1 * vo + uo;
                float cn = sigmoidf_(gf) * c1r[j] + sigmoidf_(gi) * tanhf(gc);
                float hn = sigmoidf_(go) * tanhf(cn);
                c1r[j] = cn;
                sh_h[r1 * HD + n] = hn;
                dot1 += hn * wr;
            }
        }
        #pragma unroll
        for (int off = 16; off; off >>= 1) {
            dot0 += __shfl_xor_sync(0xffffffffu, dot0, off);
            dot1 += __shfl_xor_sync(0xffffffffu, dot1, off);
        }
        y0 = dot0 + bred;   // all lanes hold the full sum after the butterfly
        y1 = dot1 + bred;
        if (l == 0) {
            out[(size_t)(row0 + r0) * TSTEPS + t] = y0;
            out[(size_t)(row0 + r1) * TSTEPS + t] = y1;
        }
        // next step's first __syncthreads (after wait_group) publishes sh_h
    }
}

extern "C" void kernel_launch(void* const* d_in, const int* in_sizes, int n_in,
                              void* d_out, int out_size) {
    const float* enc    = (const float*)d_in[0];
    const float* finalx = (const float*)d_in[1];
    const float* W_emb  = (const float*)d_in[2];
    const float* b_emb  = (const float*)d_in[3];
    const float* W_enc  = (const float*)d_in[4];
    const float* b_enc  = (const float*)d_in[5];
    const float* W_k    = (const float*)d_in[6];
    const float* W_r    = (const float*)d_in[7];
    const float* b_lstm = (const float*)d_in[8];
    const float* W_red  = (const float*)d_in[9];
    const float* b_red  = (const float*)d_in[10];
    float* out = (float*)d_out;

    int smem_bytes = (ROWS * HD + 2 * KT * GD + ROWS * KT0 + 2 * GD + HD) * (int)sizeof(float);
    cudaFuncSetAttribute(lstm_decode_kernel,
                         cudaFuncAttributeMaxDynamicSharedMemorySize, smem_bytes);

    precompute_vu_kernel<<<1, 1024>>>(W_emb, b_emb, W_k, b_lstm);
    lstm_decode_kernel<<<BATCH / ROWS, NTHR, smem_bytes>>>(
        enc, finalx, W_enc, b_enc, W_r, W_red, b_red, out);
}

// round 4
// speedup vs baseline: 1.0003x; 1.0003x over previous
#include <cuda_runtime.h>
#include <math.h>

#define BATCH   16384
#define ENCD    512
#define HD      256
#define GD      1024
#define TSTEPS  64
#define ROWS    32
#define NTHR    512
#define KT      16
#define NTILE   (HD / KT)   // 16
#define KT0     32

// v[j] = W_emb @ W_k[:,j] ; u[j] = b_emb @ W_k[:,j] + b_lstm[j]
__device__ float g_v[GD];
__device__ float g_u[GD];

__global__ void precompute_vu_kernel(const float* __restrict__ W_emb,
                                     const float* __restrict__ b_emb,
                                     const float* __restrict__ W_k,
                                     const float* __restrict__ b_lstm) {
    int j = blockIdx.x * blockDim.x + threadIdx.x;
    if (j < GD) {
        float v = 0.f, u = 0.f;
        #pragma unroll
        for (int d = 0; d < 32; ++d) {
            float wk = W_k[d * GD + j];
            v += W_emb[d] * wk;
            u += b_emb[d] * wk;
        }
        g_v[j] = v;
        g_u[j] = u + b_lstm[j];
    }
}

__device__ __forceinline__ float sigmoidf_(float x) {
    return 1.f / (1.f + __expf(-x));
}

__device__ __forceinline__ void cp16(float* dst, const float* src) {
    unsigned s = (unsigned)__cvta_generic_to_shared(dst);
    asm volatile("cp.async.cg.shared.global [%0], [%1], 16;" :: "r"(s), "l"(src));
}

// One CTA owns ROWS=32 batch rows for the whole T=64 recurrence.
// Warp w owns rows 2w,2w+1 completely (lane l -> cols 8l..8l+7, all 4 gates).
// h lives in SMEM (cross-warp GEMM input); c, y live in registers.
// W_r streamed L2->SMEM via cp.async, double-buffered KT=16 row tiles.
__global__ void __launch_bounds__(NTHR, 1)
lstm_decode_kernel(const float* __restrict__ enc,
                   const float* __restrict__ finalx,
                   const float* __restrict__ W_enc,
                   const float* __restrict__ b_enc,
                   const float* __restrict__ W_r,
                   const float* __restrict__ W_red,
                   const float* __restrict__ b_red,
                   float* __restrict__ out)
{
    extern __shared__ float smem[];
    float* sh_h    = smem;                    // ROWS*HD  = 8192
    float* sh_w0   = sh_h + ROWS * HD;        // KT*GD    = 16384
    float* sh_w1   = sh_w0 + KT * GD;         // KT*GD    = 16384
    float* sh_enc  = sh_w1 + KT * GD;         // ROWS*KT0 = 1024
    float* sh_v    = sh_enc + ROWS * KT0;     // GD
    float* sh_u    = sh_v + GD;               // GD
    float* sh_wred = sh_u + GD;               // HD

    const int tid = threadIdx.x;
    const int w   = tid >> 5;
    const int l   = tid & 31;
    const int r0  = 2 * w;
    const int r1  = 2 * w + 1;
    const int nb  = l * 8;                    // this lane's column base
    const int row0 = blockIdx.x * ROWS;

    // ---- setup ----
    for (int i = tid; i < GD; i += NTHR) { sh_v[i] = g_v[i]; sh_u[i] = g_u[i]; }
    for (int i = tid; i < HD; i += NTHR) sh_wred[i] = W_red[i];

    float y0 = finalx[row0 + r0];   // step-0 gates use finalx directly (x0@W_k = finalx*v + u)
    float y1 = finalx[row0 + r1];
    float c0r[8], c1r[8];
    #pragma unroll
    for (int j = 0; j < 8; ++j) { c0r[j] = 0.f; c1r[j] = 0.f; }
    const float bred = __ldg(b_red);

    // ---- h0 = enc @ W_enc + b_enc  ([32,512]@[512,256]) ----
    {
        float a0[8], a1[8];
        #pragma unroll
        for (int j = 0; j < 8; ++j) { a0[j] = 0.f; a1[j] = 0.f; }

        for (int k0 = 0; k0 < ENCD; k0 += KT0) {
            __syncthreads();
            if (tid < 256) {  // stage enc chunk [ROWS][KT0]
                int r  = tid >> 3;
                int c4 = (tid & 7) * 4;
                *reinterpret_cast<float4*>(sh_enc + r * KT0 + c4) =
                    *reinterpret_cast<const float4*>(enc + (size_t)(row0 + r) * ENCD + k0 + c4);
            }
            #pragma unroll
            for (int s = 0; s < 4; ++s) {  // stage W_enc chunk [KT0][HD]
                int slot = tid + s * NTHR;     // 0..2047
                int kk = slot >> 6;
                int c4 = (slot & 63) * 4;
                *reinterpret_cast<float4*>(sh_w0 + kk * HD + c4) =
                    *reinterpret_cast<const float4*>(W_enc + (size_t)(k0 + kk) * HD + c4);
            }
            __syncthreads();
            #pragma unroll
            for (int kk = 0; kk < KT0; ++kk) {
                float av0 = sh_enc[r0 * KT0 + kk];
                float av1 = sh_enc[r1 * KT0 + kk];
                float4 b0 = *reinterpret_cast<const float4*>(sh_w0 + kk * HD + nb);
                float4 b1 = *reinterpret_cast<const float4*>(sh_w0 + kk * HD + nb + 4);
                a0[0] += av0 * b0.x; a0[1] += av0 * b0.y; a0[2] += av0 * b0.z; a0[3] += av0 * b0.w;
                a0[4] += av0 * b1.x; a0[5] += av0 * b1.y; a0[6] += av0 * b1.z; a0[7] += av0 * b1.w;
                a1[0] += av1 * b0.x; a1[1] += av1 * b0.y; a1[2] += av1 * b0.z; a1[3] += av1 * b0.w;
                a1[4] += av1 * b1.x; a1[5] += av1 * b1.y; a1[6] += av1 * b1.z; a1[7] += av1 * b1.w;
            }
        }
        __syncthreads();   // all h0 FMA reads of sh_w0 done
        #pragma unroll
        for (int j = 0; j < 8; ++j) {
            float be = __ldg(b_enc + nb + j);
            sh_h[r0 * HD + nb + j] = a0[j] + be;
            sh_h[r1 * HD + nb + j] = a1[j] + be;
        }
    }

    // ---- prefetch W_r tile 0 into sh_w0 ----
    {
        #pragma unroll
        for (int s = 0; s < 8; ++s) {
            int slot = tid + s * NTHR;         // 0..4095
            int kk = slot >> 8;                // 0..15
            int c4 = (slot & 255) * 4;         // 0..1020
            cp16(sh_w0 + kk * GD + c4, W_r + (size_t)kk * GD + c4);
        }
        asm volatile("cp.async.commit_group;");
    }

    // ---- time loop ----
    for (int t = 0; t < TSTEPS; ++t) {
        float acc[2][4][8];
        #pragma unroll
        for (int i = 0; i < 2; ++i)
            #pragma unroll
            for (int g = 0; g < 4; ++g)
                #pragma unroll
                for (int j = 0; j < 8; ++j) acc[i][g][j] = 0.f;

        for (int jt = 0; jt < NTILE; ++jt) {
            // stage next tile (tile jt+1, or tile 0 again for the next step)
            {
                int nxt = (jt + 1) & (NTILE - 1);
                float* dst = ((jt + 1) & 1) ? sh_w1 : sh_w0;
                const float* src = W_r + (size_t)(nxt * KT) * GD;
                #pragma unroll
                for (int s = 0; s < 8; ++s) {
                    int slot = tid + s * NTHR;
                    int kk = slot >> 8;
                    int c4 = (slot & 255) * 4;
                    cp16(dst + kk * GD + c4, src + (size_t)kk * GD + c4);
                }
                asm volatile("cp.async.commit_group;");
            }
            asm volatile("cp.async.wait_group 1;");   // tile jt landed
            __syncthreads();                          // (also publishes sh_h at jt==0)

            const float* buf = (jt & 1) ? sh_w1 : sh_w0;
            #pragma unroll
            for (int kk = 0; kk < KT; ++kk) {
                int k = jt * KT + kk;
                float av0 = sh_h[r0 * HD + k];        // warp-uniform broadcast
                float av1 = sh_h[r1 * HD + k];
                #pragma unroll
                for (int g = 0; g < 4; ++g) {
                    float4 b0 = *reinterpret_cast<const float4*>(buf + kk * GD + g * HD + nb);
                    float4 b1 = *reinterpret_cast<const float4*>(buf + kk * GD + g * HD + nb + 4);
                    acc[0][g][0] += av0 * b0.x; acc[0][g][1] += av0 * b0.y;
                    acc[0][g][2] += av0 * b0.z; acc[0][g][3] += av0 * b0.w;
                    acc[0][g][4] += av0 * b1.x; acc[0][g][5] += av0 * b1.y;
                    acc[0][g][6] += av0 * b1.z; acc[0][g][7] += av0 * b1.w;
                    acc[1][g][0] += av1 * b0.x; acc[1][g][1] += av1 * b0.y;
                    acc[1][g][2] += av1 * b0.z; acc[1][g][3] += av1 * b0.w;
                    acc[1][g][4] += av1 * b1.x; acc[1][g][5] += av1 * b1.y;
                    acc[1][g][6] += av1 * b1.z; acc[1][g][7] += av1 * b1.w;
                }
            }
            __syncthreads();   // buffer free for restaging next iteration
        }

        // ---- fused gates + state update + warp-local y reduction ----
        float dot0 = 0.f, dot1 = 0.f;
        #pragma unroll
        for (int j = 0; j < 8; ++j) {
            int n = nb + j;
            float vi = sh_v[n],          ui = sh_u[n];
            float vf = sh_v[HD + n],     uf = sh_u[HD + n];
            float vc = sh_v[2 * HD + n], uc = sh_u[2 * HD + n];
            float vo = sh_v[3 * HD + n], uo = sh_u[3 * HD + n];
            float wr = sh_wred[n];
            {
                float gi = acc[0][0][j] + y0 * vi + ui;
                float gf = acc[0][1][j] + y0 * vf + uf;
                float gc = acc[0][2][j] + y0 * vc + uc;
                float go = acc[0][3][j] + y0 * vo + uo;
                float cn = sigmoidf_(gf) * c0r[j] + sigmoidf_(gi) * tanhf(gc);
                float hn = sigmoidf_(go) * tanhf(cn);
                c0r[j] = cn;
                sh_h[r0 * HD + n] = hn;
                dot0 += hn * wr;
            }
            {
                float gi = acc[1][0][j] + y1 * vi + ui;
                float gf = acc[1][1][j] + y1 * vf + uf;
                float gc = acc[1][2][j] + y1 * vc + uc;
                float go = acc[1][3][j] + y1 * vo + uo;
                float cn = sigmoidf_(gf) * c1r[j] + sigmoidf_(gi) * tanhf(gc);
                float hn = sigmoidf_(go) * tanhf(cn);
                c1r[j] = cn;
                sh_h[r1 * HD + n] = hn;
                dot1 += hn * wr;
            }
        }
        #pragma unroll
        for (int off = 16; off; off >>= 1) {
            dot0 += __shfl_xor_sync(0xffffffffu, dot0, off);
            dot1 += __shfl_xor_sync(0xffffffffu, dot1, off);
        }
        y0 = dot0 + bred;   // all lanes hold the full sum after the butterfly
        y1 = dot1 + bred;
        if (l == 0) {
            out[(size_t)(row0 + r0) * TSTEPS + t] = y0;
            out[(size_t)(row0 + r1) * TSTEPS + t] = y1;
        }
        // next step's first __syncthreads (after wait_group) publishes sh_h
    }
}

extern "C" void kernel_launch(void* const* d_in, const int* in_sizes, int n_in,
                              void* d_out, int out_size) {
    const float* enc    = (const float*)d_in[0];
    const float* finalx = (const float*)d_in[1];
    const float* W_emb  = (const float*)d_in[2];
    const float* b_emb  = (const float*)d_in[3];
    const float* W_enc  = (const float*)d_in[4];
    const float* b_enc  = (const float*)d_in[5];
    const float* W_k    = (const float*)d_in[6];
    const float* W_r    = (const float*)d_in[7];
    const float* b_lstm = (const float*)d_in[8];
    const float* W_red  = (const float*)d_in[9];
    const float* b_red  = (const float*)d_in[10];
    float* out = (float*)d_out;

    int smem_bytes = (ROWS * HD + 2 * KT * GD + ROWS * KT0 + 2 * GD + HD) * (int)sizeof(float);
    cudaFuncSetAttribute(lstm_decode_kernel,
                         cudaFuncAttributeMaxDynamicSharedMemorySize, smem_bytes);

    precompute_vu_kernel<<<1, 1024>>>(W_emb, b_emb, W_k, b_lstm);
    lstm_decode_kernel<<<BATCH / ROWS, NTHR, smem_bytes>>>(
        enc, finalx, W_enc, b_enc, W_r, W_red, b_red, out);
}

// round 5
// speedup vs baseline: 2.3161x; 2.3153x over previous
#include <cuda_runtime.h>
#include <math.h>

#define BATCH   16384
#define ENCD    512
#define HD      256
#define GD      1024
#define TSTEPS  64
#define ROWS    32
#define NTHR    512
#define KT      16
#define NTILE   (HD / KT)   // 16
#define KT0     32

// v[j] = W_emb @ W_k[:,j] ; u[j] = b_emb @ W_k[:,j] + b_lstm[j]
__device__ float g_v[GD];
__device__ float g_u[GD];

__global__ void precompute_vu_kernel(const float* __restrict__ W_emb,
                                     const float* __restrict__ b_emb,
                                     const float* __restrict__ W_k,
                                     const float* __restrict__ b_lstm) {
    int j = blockIdx.x * blockDim.x + threadIdx.x;
    if (j < GD) {
        float v = 0.f, u = 0.f;
        #pragma unroll
        for (int d = 0; d < 32; ++d) {
            float wk = W_k[d * GD + j];
            v += W_emb[d] * wk;
            u += b_emb[d] * wk;
        }
        g_v[j] = v;
        g_u[j] = u + b_lstm[j];
    }
}

__device__ __forceinline__ float sigmoidf_(float x) {
    return 1.f / (1.f + __expf(-x));
}

__device__ __forceinline__ void cp16(float* dst, const float* src) {
    unsigned s = (unsigned)__cvta_generic_to_shared(dst);
    asm volatile("cp.async.cg.shared.global [%0], [%1], 16;" :: "r"(s), "l"(src));
}

// CTA owns ROWS=32 rows for all T=64 steps.
// Warp = (row-group of 8 rows) x (col-group of 64 h-cols).
// Lane owns 2 h-cols (all 4 gates) x 8 rows -> 64 fp32 accumulators.
// Each W_r element is read by only 4 warps (one per row-group) -> 4x less
// LDS traffic than the previous all-cols-per-warp map.
// c-state and y live in registers. W_r double-buffered via cp.async.
__global__ void __launch_bounds__(NTHR, 1)
lstm_decode_kernel(const float* __restrict__ enc,
                   const float* __restrict__ finalx,
                   const float* __restrict__ W_enc,
                   const float* __restrict__ b_enc,
                   const float* __restrict__ W_r,
                   const float* __restrict__ W_red,
                   const float* __restrict__ b_red,
                   float* __restrict__ out)
{
    extern __shared__ float smem[];
    float* sh_h    = smem;                    // ROWS*HD  = 8192
    float* sh_w0   = sh_h + ROWS * HD;        // KT*GD    = 16384
    float* sh_w1   = sh_w0 + KT * GD;         // KT*GD    = 16384
    float* sh_enc  = sh_w1 + KT * GD;         // ROWS*KT0 = 1024
    float* sh_v    = sh_enc + ROWS * KT0;     // GD
    float* sh_u    = sh_v + GD;               // GD
    float* sh_wred = sh_u + GD;               // HD
    float* sh_part = sh_wred + HD;            // ROWS*4

    const int tid  = threadIdx.x;
    const int w    = tid >> 5;
    const int l    = tid & 31;
    const int rg   = w >> 2;              // 0..3  row group
    const int cgrp = w & 3;               // 0..3  col group
    const int rbase = rg * 8;             // rows rbase..rbase+7
    const int nb0   = cgrp * 64 + 2 * l;  // h-col pair base
    const int row0  = blockIdx.x * ROWS;

    // ---- setup ----
    for (int i = tid; i < GD; i += NTHR) { sh_v[i] = g_v[i]; sh_u[i] = g_u[i]; }
    for (int i = tid; i < HD; i += NTHR) sh_wred[i] = W_red[i];

    float yv[8];                  // y per owned row (step-0: finalx feeds gates)
    #pragma unroll
    for (int i = 0; i < 8; ++i) yv[i] = finalx[row0 + rbase + i];
    float cst[8][2];
    #pragma unroll
    for (int i = 0; i < 8; ++i) { cst[i][0] = 0.f; cst[i][1] = 0.f; }
    const float bred = __ldg(b_red);

    // ---- h0 = enc @ W_enc + b_enc  ([32,512]@[512,256]) ----
    {
        const int r0h = 2 * w, r1h = 2 * w + 1;   // h0-local mapping
        const int nbh = l * 8;
        float a0[8], a1[8];
        #pragma unroll
        for (int j = 0; j < 8; ++j) { a0[j] = 0.f; a1[j] = 0.f; }

        for (int k0 = 0; k0 < ENCD; k0 += KT0) {
            __syncthreads();
            if (tid < 256) {  // stage enc chunk [ROWS][KT0]
                int r  = tid >> 3;
                int c4 = (tid & 7) * 4;
                *reinterpret_cast<float4*>(sh_enc + r * KT0 + c4) =
                    *reinterpret_cast<const float4*>(enc + (size_t)(row0 + r) * ENCD + k0 + c4);
            }
            #pragma unroll
            for (int s = 0; s < 4; ++s) {  // stage W_enc chunk [KT0][HD]
                int slot = tid + s * NTHR;
                int kk = slot >> 6;
                int c4 = (slot & 63) * 4;
                *reinterpret_cast<float4*>(sh_w0 + kk * HD + c4) =
                    *reinterpret_cast<const float4*>(W_enc + (size_t)(k0 + kk) * HD + c4);
            }
            __syncthreads();
            #pragma unroll
            for (int kk = 0; kk < KT0; ++kk) {
                float av0 = sh_enc[r0h * KT0 + kk];
                float av1 = sh_enc[r1h * KT0 + kk];
                float4 b0 = *reinterpret_cast<const float4*>(sh_w0 + kk * HD + nbh);
                float4 b1 = *reinterpret_cast<const float4*>(sh_w0 + kk * HD + nbh + 4);
                a0[0] += av0 * b0.x; a0[1] += av0 * b0.y; a0[2] += av0 * b0.z; a0[3] += av0 * b0.w;
                a0[4] += av0 * b1.x; a0[5] += av0 * b1.y; a0[6] += av0 * b1.z; a0[7] += av0 * b1.w;
                a1[0] += av1 * b0.x; a1[1] += av1 * b0.y; a1[2] += av1 * b0.z; a1[3] += av1 * b0.w;
                a1[4] += av1 * b1.x; a1[5] += av1 * b1.y; a1[6] += av1 * b1.z; a1[7] += av1 * b1.w;
            }
        }
        __syncthreads();   // all h0 FMA reads of sh_w0 done
        #pragma unroll
        for (int j = 0; j < 8; ++j) {
            float be = __ldg(b_enc + nbh + j);
            sh_h[r0h * HD + nbh + j] = a0[j] + be;
            sh_h[r1h * HD + nbh + j] = a1[j] + be;
        }
    }

    // ---- prefetch W_r tile 0 into sh_w0 (after barrier above) ----
    {
        #pragma unroll
        for (int s = 0; s < 8; ++s) {
            int slot = tid + s * NTHR;         // 0..4095
            int kk = slot >> 8;                // 0..15
            int c4 = (slot & 255) * 4;
            cp16(sh_w0 + kk * GD + c4, W_r + (size_t)kk * GD + c4);
        }
        asm volatile("cp.async.commit_group;");
    }

    // ---- time loop ----
    for (int t = 0; t < TSTEPS; ++t) {
        float acc[8][4][2];
        #pragma unroll
        for (int i = 0; i < 8; ++i)
            #pragma unroll
            for (int g = 0; g < 4; ++g) { acc[i][g][0] = 0.f; acc[i][g][1] = 0.f; }

        for (int jt = 0; jt < NTILE; ++jt) {
            {   // stage tile jt+1 (wraps to tile 0 for next step)
                int nxt = (jt + 1) & (NTILE - 1);
                float* dst = ((jt + 1) & 1) ? sh_w1 : sh_w0;
                const float* src = W_r + (size_t)(nxt * KT) * GD;
                #pragma unroll
                for (int s = 0; s < 8; ++s) {
                    int slot = tid + s * NTHR;
                    int kk = slot >> 8;
                    int c4 = (slot & 255) * 4;
                    cp16(dst + kk * GD + c4, src + (size_t)kk * GD + c4);
                }
                asm volatile("cp.async.commit_group;");
            }
            asm volatile("cp.async.wait_group 1;");   // tile jt landed
            __syncthreads();                          // publishes sh_h at jt==0 too

            const float* buf = (jt & 1) ? sh_w1 : sh_w0;
            #pragma unroll
            for (int kk = 0; kk < KT; ++kk) {
                int k = jt * KT + kk;
                float ah[8];
                #pragma unroll
                for (int i = 0; i < 8; ++i)           // warp-uniform broadcasts
                    ah[i] = sh_h[(rbase + i) * HD + k];
                const float* brow = buf + kk * GD;
                float2 bg[4];
                #pragma unroll
                for (int g = 0; g < 4; ++g)
                    bg[g] = *reinterpret_cast<const float2*>(brow + g * HD + nb0);
                #pragma unroll
                for (int i = 0; i < 8; ++i)
                    #pragma unroll
                    for (int g = 0; g < 4; ++g) {
                        acc[i][g][0] += ah[i] * bg[g].x;
                        acc[i][g][1] += ah[i] * bg[g].y;
                    }
            }
            __syncthreads();   // buffer free for restage next iteration
        }

        // ---- fused gates + state update + y reduction ----
        float part[8];
        #pragma unroll
        for (int i = 0; i < 8; ++i) {
            int r = rbase + i;
            float y = yv[i];
            float dot = 0.f;
            #pragma unroll
            for (int jj = 0; jj < 2; ++jj) {
                int n = nb0 + jj;
                float gi = acc[i][0][jj] + y * sh_v[n]          + sh_u[n];
                float gf = acc[i][1][jj] + y * sh_v[HD + n]     + sh_u[HD + n];
                float gc = acc[i][2][jj] + y * sh_v[2 * HD + n] + sh_u[2 * HD + n];
                float go = acc[i][3][jj] + y * sh_v[3 * HD + n] + sh_u[3 * HD + n];
                float cn = sigmoidf_(gf) * cst[i][jj] + sigmoidf_(gi) * tanhf(gc);
                float hn = sigmoidf_(go) * tanhf(cn);
                cst[i][jj] = cn;
                sh_h[r * HD + n] = hn;
                dot += hn * sh_wred[n];
            }
            part[i] = dot;
        }
        #pragma unroll
        for (int off = 16; off; off >>= 1)
            #pragma unroll
            for (int i = 0; i < 8; ++i)
                part[i] += __shfl_xor_sync(0xffffffffu, part[i], off);
        if (l == 0) {
            #pragma unroll
            for (int i = 0; i < 8; ++i)
                sh_part[(rbase + i) * 4 + cgrp] = part[i];
        }
        __syncthreads();
        #pragma unroll
        for (int i = 0; i < 8; ++i) {
            int r = rbase + i;
            yv[i] = sh_part[r * 4] + sh_part[r * 4 + 1]
                  + sh_part[r * 4 + 2] + sh_part[r * 4 + 3] + bred;
        }
        if (cgrp == 0 && l == 0) {
            #pragma unroll
            for (int i = 0; i < 8; ++i)
                out[(size_t)(row0 + rbase + i) * TSTEPS + t] = yv[i];
        }
        // next step's first __syncthreads (after wait_group) re-separates phases
    }
}

extern "C" void kernel_launch(void* const* d_in, const int* in_sizes, int n_in,
                              void* d_out, int out_size) {
    const float* enc    = (const float*)d_in[0];
    const float* finalx = (const float*)d_in[1];
    const float* W_emb  = (const float*)d_in[2];
    const float* b_emb  = (const float*)d_in[3];
    const float* W_enc  = (const float*)d_in[4];
    const float* b_enc  = (const float*)d_in[5];
    const float* W_k    = (const float*)d_in[6];
    const float* W_r    = (const float*)d_in[7];
    const float* b_lstm = (const float*)d_in[8];
    const float* W_red  = (const float*)d_in[9];
    const float* b_red  = (const float*)d_in[10];
    float* out = (float*)d_out;

    int smem_bytes = (ROWS * HD + 2 * KT * GD + ROWS * KT0 + 2 * GD + HD + ROWS * 4)
                     * (int)sizeof(float);
    cudaFuncSetAttribute(lstm_decode_kernel,
                         cudaFuncAttributeMaxDynamicSharedMemorySize, smem_bytes);

    precompute_vu_kernel<<<1, 1024>>>(W_emb, b_emb, W_k, b_lstm);
    lstm_decode_kernel<<<BATCH / ROWS, NTHR, smem_bytes>>>(
        enc, finalx, W_enc, b_enc, W_r, W_red, b_red, out);
}

// round 6
// speedup vs baseline: 2.9201x; 1.2607x over previous
#include <cuda_runtime.h>
#include <math.h>

#define BATCH   16384
#define ENCD    512
#define HD      256
#define GD      1024
#define TSTEPS  64
#define ROWS    32
#define NTHR    512
#define KT      16
#define NTILE   (HD / KT)   // 16
#define KT0     32
#define HTP     36          // padded row length of transposed h (floats)

// v[j] = W_emb @ W_k[:,j] ; u[j] = b_emb @ W_k[:,j] + b_lstm[j]
__device__ float g_v[GD];
__device__ float g_u[GD];

__global__ void precompute_vu_kernel(const float* __restrict__ W_emb,
                                     const float* __restrict__ b_emb,
                                     const float* __restrict__ W_k,
                                     const float* __restrict__ b_lstm) {
    int j = blockIdx.x * blockDim.x + threadIdx.x;
    if (j < GD) {
        float v = 0.f, u = 0.f;
        #pragma unroll
        for (int d = 0; d < 32; ++d) {
            float wk = W_k[d * GD + j];
            v += W_emb[d] * wk;
            u += b_emb[d] * wk;
        }
        g_v[j] = v;
        g_u[j] = u + b_lstm[j];
    }
}

__device__ __forceinline__ float sigmoidf_(float x) {
    return 1.f / (1.f + __expf(-x));
}

__device__ __forceinline__ void cp16(float* dst, const float* src) {
    unsigned s = (unsigned)__cvta_generic_to_shared(dst);
    asm volatile("cp.async.cg.shared.global [%0], [%1], 16;" :: "r"(s), "l"(src));
}

// packed fp32x2 helpers (FFMA2 path: 2 FMAs per issue slot)
__device__ __forceinline__ void fma2(unsigned long long& acc,
                                     unsigned long long a,
                                     unsigned long long b) {
    asm("fma.rn.f32x2 %0, %1, %2, %0;" : "+l"(acc) : "l"(a), "l"(b));
}
__device__ __forceinline__ unsigned long long dup2(float x) {
    unsigned long long r;
    unsigned xi = __float_as_uint(x);
    asm("mov.b64 %0, {%1, %1};" : "=l"(r) : "r"(xi));
    return r;
}

// CTA owns ROWS=32 rows for all T=64 steps.
// Warp = (row-group of 8 rows) x (col-group of 64 h-cols); lane owns 2
// consecutive h-cols x 4 gates x 8 rows as 32 packed f32x2 accumulators.
// h is stored TRANSPOSED (sh_ht[k][row], pad 36) so A comes in as one
// warp-uniform LDS.128 broadcast per 4 rows; B comes in as LDS.64 pairs
// feeding fma.rn.f32x2 directly. c-state and y live in registers.
// W_r double-buffered KT=16-row tiles via cp.async.
__global__ void __launch_bounds__(NTHR, 1)
lstm_decode_kernel(const float* __restrict__ enc,
                   const float* __restrict__ finalx,
                   const float* __restrict__ W_enc,
                   const float* __restrict__ b_enc,
                   const float* __restrict__ W_r,
                   const float* __restrict__ W_red,
                   const float* __restrict__ b_red,
                   float* __restrict__ out)
{
    extern __shared__ float smem[];
    float* sh_ht   = smem;                    // HD*HTP   = 9216
    float* sh_w0   = sh_ht + HD * HTP;        // KT*GD    = 16384
    float* sh_w1   = sh_w0 + KT * GD;         // KT*GD    = 16384
    float* sh_enc  = sh_w1 + KT * GD;         // ROWS*KT0 = 1024
    float* sh_v    = sh_enc + ROWS * KT0;     // GD
    float* sh_u    = sh_v + GD;               // GD
    float* sh_wred = sh_u + GD;               // HD
    float* sh_part = sh_wred + HD;            // ROWS*4

    const int tid  = threadIdx.x;
    const int w    = tid >> 5;
    const int l    = tid & 31;
    const int rg   = w >> 2;              // 0..3  row group
    const int cgrp = w & 3;               // 0..3  col group
    const int rbase = rg * 8;             // rows rbase..rbase+7
    const int nb0   = cgrp * 64 + 2 * l;  // h-col pair base
    const int row0  = blockIdx.x * ROWS;

    // ---- setup ----
    for (int i = tid; i < GD; i += NTHR) { sh_v[i] = g_v[i]; sh_u[i] = g_u[i]; }
    for (int i = tid; i < HD; i += NTHR) sh_wred[i] = W_red[i];

    float yv[8];                  // y per owned row (step-0: finalx feeds gates)
    #pragma unroll
    for (int i = 0; i < 8; ++i) yv[i] = finalx[row0 + rbase + i];
    float cst[8][2];
    #pragma unroll
    for (int i = 0; i < 8; ++i) { cst[i][0] = 0.f; cst[i][1] = 0.f; }
    const float bred = __ldg(b_red);

    // ---- h0 = enc @ W_enc + b_enc  ([32,512]@[512,256]) ----
    {
        const int r0h = 2 * w, r1h = 2 * w + 1;   // h0-local mapping
        const int nbh = l * 8;
        float a0[8], a1[8];
        #pragma unroll
        for (int j = 0; j < 8; ++j) { a0[j] = 0.f; a1[j] = 0.f; }

        for (int k0 = 0; k0 < ENCD; k0 += KT0) {
            __syncthreads();
            if (tid < 256) {  // stage enc chunk [ROWS][KT0]
                int r  = tid >> 3;
                int c4 = (tid & 7) * 4;
                *reinterpret_cast<float4*>(sh_enc + r * KT0 + c4) =
                    *reinterpret_cast<const float4*>(enc + (size_t)(row0 + r) * ENCD + k0 + c4);
            }
            #pragma unroll
            for (int s = 0; s < 4; ++s) {  // stage W_enc chunk [KT0][HD]
                int slot = tid + s * NTHR;
                int kk = slot >> 6;
                int c4 = (slot & 63) * 4;
                *reinterpret_cast<float4*>(sh_w0 + kk * HD + c4) =
                    *reinterpret_cast<const float4*>(W_enc + (size_t)(k0 + kk) * HD + c4);
            }
            __syncthreads();
            #pragma unroll
            for (int kk = 0; kk < KT0; ++kk) {
                float av0 = sh_enc[r0h * KT0 + kk];
                float av1 = sh_enc[r1h * KT0 + kk];
                float4 b0 = *reinterpret_cast<const float4*>(sh_w0 + kk * HD + nbh);
                float4 b1 = *reinterpret_cast<const float4*>(sh_w0 + kk * HD + nbh + 4);
                a0[0] += av0 * b0.x; a0[1] += av0 * b0.y; a0[2] += av0 * b0.z; a0[3] += av0 * b0.w;
                a0[4] += av0 * b1.x; a0[5] += av0 * b1.y; a0[6] += av0 * b1.z; a0[7] += av0 * b1.w;
                a1[0] += av1 * b0.x; a1[1] += av1 * b0.y; a1[2] += av1 * b0.z; a1[3] += av1 * b0.w;
                a1[4] += av1 * b1.x; a1[5] += av1 * b1.y; a1[6] += av1 * b1.z; a1[7] += av1 * b1.w;
            }
        }
        __syncthreads();   // all h0 FMA reads of sh_w0 done
        #pragma unroll
        for (int j = 0; j < 8; ++j) {
            float be = __ldg(b_enc + nbh + j);
            sh_ht[(nbh + j) * HTP + r0h] = a0[j] + be;   // transposed store
            sh_ht[(nbh + j) * HTP + r1h] = a1[j] + be;
        }
    }

    // ---- prefetch W_r tile 0 into sh_w0 (after barrier above) ----
    {
        #pragma unroll
        for (int s = 0; s < 8; ++s) {
            int slot = tid + s * NTHR;         // 0..4095
            int kk = slot >> 8;                // 0..15
            int c4 = (slot & 255) * 4;
            cp16(sh_w0 + kk * GD + c4, W_r + (size_t)kk * GD + c4);
        }
        asm volatile("cp.async.commit_group;");
    }

    // ---- time loop ----
    for (int t = 0; t < TSTEPS; ++t) {
        // packed accumulators: acc[i][g] = {gate g, cols nb0 / nb0+1}, row rbase+i
        unsigned long long acc[8][4];
        #pragma unroll
        for (int i = 0; i < 8; ++i)
            #pragma unroll
            for (int g = 0; g < 4; ++g) acc[i][g] = 0ULL;

        for (int jt = 0; jt < NTILE; ++jt) {
            {   // stage tile jt+1 (wraps to tile 0 for next step)
                int nxt = (jt + 1) & (NTILE - 1);
                float* dst = ((jt + 1) & 1) ? sh_w1 : sh_w0;
                const float* src = W_r + (size_t)(nxt * KT) * GD;
                #pragma unroll
                for (int s = 0; s < 8; ++s) {
                    int slot = tid + s * NTHR;
                    int kk = slot >> 8;
                    int c4 = (slot & 255) * 4;
                    cp16(dst + kk * GD + c4, src + (size_t)kk * GD + c4);
                }
                asm volatile("cp.async.commit_group;");
            }
            asm volatile("cp.async.wait_group 1;");   // tile jt landed
            __syncthreads();                          // publishes sh_ht at jt==0 too

            const float* buf = (jt & 1) ? sh_w1 : sh_w0;
            #pragma unroll
            for (int kk = 0; kk < KT; ++kk) {
                int k = jt * KT + kk;
                // A: 8 rows via two uniform LDS.128 broadcasts + dup-pack
                float4 aA = *reinterpret_cast<const float4*>(sh_ht + k * HTP + rbase);
                float4 aB = *reinterpret_cast<const float4*>(sh_ht + k * HTP + rbase + 4);
                unsigned long long ap[8];
                ap[0] = dup2(aA.x); ap[1] = dup2(aA.y);
                ap[2] = dup2(aA.z); ap[3] = dup2(aA.w);
                ap[4] = dup2(aB.x); ap[5] = dup2(aB.y);
                ap[6] = dup2(aB.z); ap[7] = dup2(aB.w);
                const float* brow = buf + kk * GD;
                unsigned long long bg[4];
                #pragma unroll
                for (int g = 0; g < 4; ++g)
                    bg[g] = *reinterpret_cast<const unsigned long long*>(brow + g * HD + nb0);
                #pragma unroll
                for (int i = 0; i < 8; ++i)
                    #pragma unroll
                    for (int g = 0; g < 4; ++g)
                        fma2(acc[i][g], ap[i], bg[g]);
            }
            __syncthreads();   // buffer free for restage next iteration
        }

        // ---- fused gates + state update + y reduction ----
        float part[8];
        #pragma unroll
        for (int i = 0; i < 8; ++i) {
            int r = rbase + i;
            float y = yv[i];
            float dot = 0.f;
            float ga[4][2];
            #pragma unroll
            for (int g = 0; g < 4; ++g) {
                ga[g][0] = __uint_as_float((unsigned)(acc[i][g]));
                ga[g][1] = __uint_as_float((unsigned)(acc[i][g] >> 32));
            }
            #pragma unroll
            for (int jj = 0; jj < 2; ++jj) {
                int n = nb0 + jj;
                float gi = ga[0][jj] + y * sh_v[n]          + sh_u[n];
                float gf = ga[1][jj] + y * sh_v[HD + n]     + sh_u[HD + n];
                float gc = ga[2][jj] + y * sh_v[2 * HD + n] + sh_u[2 * HD + n];
                float go = ga[3][jj] + y * sh_v[3 * HD + n] + sh_u[3 * HD + n];
                float cn = sigmoidf_(gf) * cst[i][jj] + sigmoidf_(gi) * tanhf(gc);
                float hn = sigmoidf_(go) * tanhf(cn);
                cst[i][jj] = cn;
                sh_ht[n * HTP + r] = hn;          // transposed store
                dot += hn * sh_wred[n];
            }
            part[i] = dot;
        }
        #pragma unroll
        for (int off = 16; off; off >>= 1)
            #pragma unroll
            for (int i = 0; i < 8; ++i)
                part[i] += __shfl_xor_sync(0xffffffffu, part[i], off);
        if (l == 0) {
            #pragma unroll
            for (int i = 0; i < 8; ++i)
                sh_part[(rbase + i) * 4 + cgrp] = part[i];
        }
        __syncthreads();
        #pragma unroll
        for (int i = 0; i < 8; ++i) {
            int r = rbase + i;
            yv[i] = sh_part[r * 4] + sh_part[r * 4 + 1]
                  + sh_part[r * 4 + 2] + sh_part[r * 4 + 3] + bred;
        }
        if (cgrp == 0 && l == 0) {
            #pragma unroll
            for (int i = 0; i < 8; ++i)
                out[(size_t)(row0 + rbase + i) * TSTEPS + t] = yv[i];
        }
        // next step's first __syncthreads (after wait_group) re-separates phases
    }
}

extern "C" void kernel_launch(void* const* d_in, const int* in_sizes, int n_in,
                              void* d_out, int out_size) {
    const float* enc    = (const float*)d_in[0];
    const float* finalx = (const float*)d_in[1];
    const float* W_emb  = (const float*)d_in[2];
    const float* b_emb  = (const float*)d_in[3];
    const float* W_enc  = (const float*)d_in[4];
    const float* b_enc  = (const float*)d_in[5];
    const float* W_k    = (const float*)d_in[6];
    const float* W_r    = (const float*)d_in[7];
    const float* b_lstm = (const float*)d_in[8];
    const float* W_red  = (const float*)d_in[9];
    const float* b_red  = (const float*)d_in[10];
    float* out = (float*)d_out;

    int smem_bytes = (HD * HTP + 2 * KT * GD + ROWS * KT0 + 2 * GD + HD + ROWS * 4)
                     * (int)sizeof(float);
    cudaFuncSetAttribute(lstm_decode_kernel,
                         cudaFuncAttributeMaxDynamicSharedMemorySize, smem_bytes);

    precompute_vu_kernel<<<1, 1024>>>(W_emb, b_emb, W_k, b_lstm);
    lstm_decode_kernel<<<BATCH / ROWS, NTHR, smem_bytes>>>(
        enc, finalx, W_enc, b_enc, W_r, W_red, b_red, out);
}

// round 7
// speedup vs baseline: 2.9223x; 1.0008x over previous
#include <cuda_runtime.h>
#include <math.h>

#define BATCH   16384
#define ENCD    512
#define HD      256
#define GD      1024
#define TSTEPS  64
#define ROWS    32
#define NTHR    512
#define KT      16
#define NTILE   (HD / KT)   // 16
#define KT0     32
#define HTP     36          // padded row length of transposed h (floats)

// v[j] = W_emb @ W_k[:,j] ; u[j] = b_emb @ W_k[:,j] + b_lstm[j]
__device__ float g_v[GD];
__device__ float g_u[GD];

__global__ void precompute_vu_kernel(const float* __restrict__ W_emb,
                                     const float* __restrict__ b_emb,
                                     const float* __restrict__ W_k,
                                     const float* __restrict__ b_lstm) {
    int j = blockIdx.x * blockDim.x + threadIdx.x;
    if (j < GD) {
        float v = 0.f, u = 0.f;
        #pragma unroll
        for (int d = 0; d < 32; ++d) {
            float wk = W_k[d * GD + j];
            v += W_emb[d] * wk;
            u += b_emb[d] * wk;
        }
        g_v[j] = v;
        g_u[j] = u + b_lstm[j];
    }
}

__device__ __forceinline__ float sigmoidf_(float x) {
    return 1.f / (1.f + __expf(-x));
}

__device__ __forceinline__ void cp16(float* dst, const float* src) {
    unsigned s = (unsigned)__cvta_generic_to_shared(dst);
    asm volatile("cp.async.cg.shared.global [%0], [%1], 16;" :: "r"(s), "l"(src));
}

// packed fp32x2 helpers (FFMA2 path: 2 FMAs per issue slot)
__device__ __forceinline__ void fma2(unsigned long long& acc,
                                     unsigned long long a,
                                     unsigned long long b) {
    asm("fma.rn.f32x2 %0, %1, %2, %0;" : "+l"(acc) : "l"(a), "l"(b));
}
__device__ __forceinline__ unsigned long long dup2(float x) {
    unsigned long long r;
    unsigned xi = __float_as_uint(x);
    asm("mov.b64 %0, {%1, %1};" : "=l"(r) : "r"(xi));
    return r;
}

// CTA owns ROWS=32 rows for all T=64 steps.
// Warp = (row-group of 8 rows) x (col-group of 64 h-cols); lane owns 2
// consecutive h-cols x 4 gates x 8 rows as 32 packed f32x2 accumulators.
// h is stored TRANSPOSED (sh_ht[k][row], pad 36) so A comes in as one
// warp-uniform LDS.128 broadcast per 4 rows; B comes in as LDS.64 pairs
// feeding fma.rn.f32x2 directly. c-state and y live in registers.
// W_r double-buffered KT=16-row tiles via cp.async.
__global__ void __launch_bounds__(NTHR, 1)
lstm_decode_kernel(const float* __restrict__ enc,
                   const float* __restrict__ finalx,
                   const float* __restrict__ W_enc,
                   const float* __restrict__ b_enc,
                   const float* __restrict__ W_r,
                   const float* __restrict__ W_red,
                   const float* __restrict__ b_red,
                   float* __restrict__ out)
{
    extern __shared__ float smem[];
    float* sh_ht   = smem;                    // HD*HTP   = 9216
    float* sh_w0   = sh_ht + HD * HTP;        // KT*GD    = 16384
    float* sh_w1   = sh_w0 + KT * GD;         // KT*GD    = 16384
    float* sh_enc  = sh_w1 + KT * GD;         // ROWS*KT0 = 1024
    float* sh_v    = sh_enc + ROWS * KT0;     // GD
    float* sh_u    = sh_v + GD;               // GD
    float* sh_wred = sh_u + GD;               // HD
    float* sh_part = sh_wred + HD;            // ROWS*4

    const int tid  = threadIdx.x;
    const int w    = tid >> 5;
    const int l    = tid & 31;
    const int rg   = w >> 2;              // 0..3  row group
    const int cgrp = w & 3;               // 0..3  col group
    const int rbase = rg * 8;             // rows rbase..rbase+7
    const int nb0   = cgrp * 64 + 2 * l;  // h-col pair base
    const int row0  = blockIdx.x * ROWS;

    // ---- setup ----
    for (int i = tid; i < GD; i += NTHR) { sh_v[i] = g_v[i]; sh_u[i] = g_u[i]; }
    for (int i = tid; i < HD; i += NTHR) sh_wred[i] = W_red[i];

    float yv[8];                  // y per owned row (step-0: finalx feeds gates)
    #pragma unroll
    for (int i = 0; i < 8; ++i) yv[i] = finalx[row0 + rbase + i];
    float cst[8][2];
    #pragma unroll
    for (int i = 0; i < 8; ++i) { cst[i][0] = 0.f; cst[i][1] = 0.f; }
    const float bred = __ldg(b_red);

    // ---- h0 = enc @ W_enc + b_enc  ([32,512]@[512,256]) ----
    {
        const int r0h = 2 * w, r1h = 2 * w + 1;   // h0-local mapping
        const int nbh = l * 8;
        float a0[8], a1[8];
        #pragma unroll
        for (int j = 0; j < 8; ++j) { a0[j] = 0.f; a1[j] = 0.f; }

        for (int k0 = 0; k0 < ENCD; k0 += KT0) {
            __syncthreads();
            if (tid < 256) {  // stage enc chunk [ROWS][KT0]
                int r  = tid >> 3;
                int c4 = (tid & 7) * 4;
                *reinterpret_cast<float4*>(sh_enc + r * KT0 + c4) =
                    *reinterpret_cast<const float4*>(enc + (size_t)(row0 + r) * ENCD + k0 + c4);
            }
            #pragma unroll
            for (int s = 0; s < 4; ++s) {  // stage W_enc chunk [KT0][HD]
                int slot = tid + s * NTHR;
                int kk = slot >> 6;
                int c4 = (slot & 63) * 4;
                *reinterpret_cast<float4*>(sh_w0 + kk * HD + c4) =
                    *reinterpret_cast<const float4*>(W_enc + (size_t)(k0 + kk) * HD + c4);
            }
            __syncthreads();
            #pragma unroll
            for (int kk = 0; kk < KT0; ++kk) {
                float av0 = sh_enc[r0h * KT0 + kk];
                float av1 = sh_enc[r1h * KT0 + kk];
                float4 b0 = *reinterpret_cast<const float4*>(sh_w0 + kk * HD + nbh);
                float4 b1 = *reinterpret_cast<const float4*>(sh_w0 + kk * HD + nbh + 4);
                a0[0] += av0 * b0.x; a0[1] += av0 * b0.y; a0[2] += av0 * b0.z; a0[3] += av0 * b0.w;
                a0[4] += av0 * b1.x; a0[5] += av0 * b1.y; a0[6] += av0 * b1.z; a0[7] += av0 * b1.w;
                a1[0] += av1 * b0.x; a1[1] += av1 * b0.y; a1[2] += av1 * b0.z; a1[3] += av1 * b0.w;
                a1[4] += av1 * b1.x; a1[5] += av1 * b1.y; a1[6] += av1 * b1.z; a1[7] += av1 * b1.w;
            }
        }
        __syncthreads();   // all h0 FMA reads of sh_w0 done
        #pragma unroll
        for (int j = 0; j < 8; ++j) {
            float be = __ldg(b_enc + nbh + j);
            sh_ht[(nbh + j) * HTP + r0h] = a0[j] + be;   // transposed store
            sh_ht[(nbh + j) * HTP + r1h] = a1[j] + be;
        }
    }

    // ---- prefetch W_r tile 0 into sh_w0 (after barrier above) ----
    {
        #pragma unroll
        for (int s = 0; s < 8; ++s) {
            int slot = tid + s * NTHR;         // 0..4095
            int kk = slot >> 8;                // 0..15
            int c4 = (slot & 255) * 4;
            cp16(sh_w0 + kk * GD + c4, W_r + (size_t)kk * GD + c4);
        }
        asm volatile("cp.async.commit_group;");
    }

    // ---- time loop ----
    for (int t = 0; t < TSTEPS; ++t) {
        // packed accumulators: acc[i][g] = {gate g, cols nb0 / nb0+1}, row rbase+i
        unsigned long long acc[8][4];
        #pragma unroll
        for (int i = 0; i < 8; ++i)
            #pragma unroll
            for (int g = 0; g < 4; ++g) acc[i][g] = 0ULL;

        for (int jt = 0; jt < NTILE; ++jt) {
            {   // stage tile jt+1 (wraps to tile 0 for next step)
                int nxt = (jt + 1) & (NTILE - 1);
                float* dst = ((jt + 1) & 1) ? sh_w1 : sh_w0;
                const float* src = W_r + (size_t)(nxt * KT) * GD;
                #pragma unroll
                for (int s = 0; s < 8; ++s) {
                    int slot = tid + s * NTHR;
                    int kk = slot >> 8;
                    int c4 = (slot & 255) * 4;
                    cp16(dst + kk * GD + c4, src + (size_t)kk * GD + c4);
                }
                asm volatile("cp.async.commit_group;");
            }
            asm volatile("cp.async.wait_group 1;");   // tile jt landed
            __syncthreads();                          // publishes sh_ht at jt==0 too

            const float* buf = (jt & 1) ? sh_w1 : sh_w0;
            #pragma unroll
            for (int kk = 0; kk < KT; ++kk) {
                int k = jt * KT + kk;
                // A: 8 rows via two uniform LDS.128 broadcasts + dup-pack
                float4 aA = *reinterpret_cast<const float4*>(sh_ht + k * HTP + rbase);
                float4 aB = *reinterpret_cast<const float4*>(sh_ht + k * HTP + rbase + 4);
                unsigned long long ap[8];
                ap[0] = dup2(aA.x); ap[1] = dup2(aA.y);
                ap[2] = dup2(aA.z); ap[3] = dup2(aA.w);
                ap[4] = dup2(aB.x); ap[5] = dup2(aB.y);
                ap[6] = dup2(aB.z); ap[7] = dup2(aB.w);
                const float* brow = buf + kk * GD;
                unsigned long long bg[4];
                #pragma unroll
                for (int g = 0; g < 4; ++g)
                    bg[g] = *reinterpret_cast<const unsigned long long*>(brow + g * HD + nb0);
                #pragma unroll
                for (int i = 0; i < 8; ++i)
                    #pragma unroll
                    for (int g = 0; g < 4; ++g)
                        fma2(acc[i][g], ap[i], bg[g]);
            }
            __syncthreads();   // buffer free for restage next iteration
        }

        // ---- fused gates + state update + y reduction ----
        float part[8];
        #pragma unroll
        for (int i = 0; i < 8; ++i) {
            int r = rbase + i;
            float y = yv[i];
            float dot = 0.f;
            float ga[4][2];
            #pragma unroll
            for (int g = 0; g < 4; ++g) {
                ga[g][0] = __uint_as_float((unsigned)(acc[i][g]));
                ga[g][1] = __uint_as_float((unsigned)(acc[i][g] >> 32));
            }
            #pragma unroll
            for (int jj = 0; jj < 2; ++jj) {
                int n = nb0 + jj;
                float gi = ga[0][jj] + y * sh_v[n]          + sh_u[n];
                float gf = ga[1][jj] + y * sh_v[HD + n]     + sh_u[HD + n];
                float gc = ga[2][jj] + y * sh_v[2 * HD + n] + sh_u[2 * HD + n];
                float go = ga[3][jj] + y * sh_v[3 * HD + n] + sh_u[3 * HD + n];
                float cn = sigmoidf_(gf) * cst[i][jj] + sigmoidf_(gi) * tanhf(gc);
                float hn = sigmoidf_(go) * tanhf(cn);
                cst[i][jj] = cn;
                sh_ht[n * HTP + r] = hn;          // transposed store
                dot += hn * sh_wred[n];
            }
            part[i] = dot;
        }
        #pragma unroll
        for (int off = 16; off; off >>= 1)
            #pragma unroll
            for (int i = 0; i < 8; ++i)
                part[i] += __shfl_xor_sync(0xffffffffu, part[i], off);
        if (l == 0) {
            #pragma unroll
            for (int i = 0; i < 8; ++i)
                sh_part[(rbase + i) * 4 + cgrp] = part[i];
        }
        __syncthreads();
        #pragma unroll
        for (int i = 0; i < 8; ++i) {
            int r = rbase + i;
            yv[i] = sh_part[r * 4] + sh_part[r * 4 + 1]
                  + sh_part[r * 4 + 2] + sh_part[r * 4 + 3] + bred;
        }
        if (cgrp == 0 && l == 0) {
            #pragma unroll
            for (int i = 0; i < 8; ++i)
                out[(size_t)(row0 + rbase + i) * TSTEPS + t] = yv[i];
        }
        // next step's first __syncthreads (after wait_group) re-separates phases
    }
}

extern "C" void kernel_launch(void* const* d_in, const int* in_sizes, int n_in,
                              void* d_out, int out_size) {
    const float* enc    = (const float*)d_in[0];
    const float* finalx = (const float*)d_in[1];
    const float* W_emb  = (const float*)d_in[2];
    const float* b_emb  = (const float*)d_in[3];
    const float* W_enc  = (const float*)d_in[4];
    const float* b_enc  = (const float*)d_in[5];
    const float* W_k    = (const float*)d_in[6];
    const float* W_r    = (const float*)d_in[7];
    const float* b_lstm = (const float*)d_in[8];
    const float* W_red  = (const float*)d_in[9];
    const float* b_red  = (const float*)d_in[10];
    float* out = (float*)d_out;

    int smem_bytes = (HD * HTP + 2 * KT * GD + ROWS * KT0 + 2 * GD + HD + ROWS * 4)
                     * (int)sizeof(float);
    cudaFuncSetAttribute(lstm_decode_kernel,
                         cudaFuncAttributeMaxDynamicSharedMemorySize, smem_bytes);

    precompute_vu_kernel<<<1, 1024>>>(W_emb, b_emb, W_k, b_lstm);
    lstm_decode_kernel<<<BATCH / ROWS, NTHR, smem_bytes>>>(
        enc, finalx, W_enc, b_enc, W_r, W_red, b_red, out);
}

// round 8
// speedup vs baseline: 4.9265x; 1.6858x over previous
#include <cuda_runtime.h>
#include <cuda_bf16.h>
#include <math.h>

#define BATCH   16384
#define ENCD    512
#define HD      256
#define GD      1024
#define TSTEPS  64
#define MROWS   64
#define NTHR    512
#define HROW    264     // padded h row length (bf16 elems)
#define HROWB   528     // bytes
#define WROWB   80      // padded W buffer row bytes (40 bf16)

// shared memory byte offsets
#define HBYTES  33792   // 64*264*2
#define WBOFF   135168  // 4*HBYTES
#define WBUFSZ  20480   // 256*40*2
#define VOFF    217088  // WBOFF + 4*WBUFSZ
#define UOFF    221184
#define WREDOFF 225280
#define YOFF    226304
#define PARTOFF 226560
#define SMEMSZ  227584

// v[j] = W_emb @ W_k[:,j] ; u[j] = b_emb @ W_k[:,j] + b_lstm[j]
__device__ float g_v[GD];
__device__ float g_u[GD];
// W_r split to bf16 hi/lo, transposed to [N][K] and permuted:
// row' = p*256 + g*64 + w64  <->  n = g*256 + p*64 + w64  (pass p streams rows p*256..p*256+255)
__device__ __nv_bfloat16 g_whi[GD * HD];
__device__ __nv_bfloat16 g_wlo[GD * HD];

__global__ void precompute_vu_kernel(const float* __restrict__ W_emb,
                                     const float* __restrict__ b_emb,
                                     const float* __restrict__ W_k,
                                     const float* __restrict__ b_lstm) {
    int j = blockIdx.x * blockDim.x + threadIdx.x;
    if (j < GD) {
        float v = 0.f, u = 0.f;
        #pragma unroll
        for (int d = 0; d < 32; ++d) {
            float wk = W_k[d * GD + j];
            v += W_emb[d] * wk;
            u += b_emb[d] * wk;
        }
        g_v[j] = v;
        g_u[j] = u + b_lstm[j];
    }
}

__global__ void precompute_w_kernel(const float* __restrict__ W_r) {
    int idx = blockIdx.x * blockDim.x + threadIdx.x;   // 0 .. GD*HD-1
    if (idx < GD * HD) {
        int row = idx >> 8;          // row' 0..1023
        int k   = idx & 255;
        int p   = row >> 8;
        int rem = row & 255;
        int g   = rem >> 6;
        int w64 = rem & 63;
        int n   = g * 256 + p * 64 + w64;
        float val = W_r[(size_t)k * GD + n];
        __nv_bfloat16 hi = __float2bfloat16(val);
        __nv_bfloat16 lo = __float2bfloat16(val - __bfloat162float(hi));
        g_whi[idx] = hi;
        g_wlo[idx] = lo;
    }
}

__device__ __forceinline__ float sigmoidf_(float x) {
    return __fdividef(1.f, 1.f + __expf(-x));
}
__device__ __forceinline__ float tanh_fast(float x) {
    float e = __expf(-2.f * x);
    return __fdividef(1.f - e, 1.f + e);
}

__device__ __forceinline__ void cp16(void* dst, const void* src) {
    unsigned s = (unsigned)__cvta_generic_to_shared(dst);
    asm volatile("cp.async.cg.shared.global [%0], [%1], 16;" :: "r"(s), "l"(src));
}

__device__ __forceinline__ void ldm_x4(unsigned* r, unsigned addr) {
    asm volatile("ldmatrix.sync.aligned.m8n8.x4.shared.b16 {%0,%1,%2,%3}, [%4];"
                 : "=r"(r[0]), "=r"(r[1]), "=r"(r[2]), "=r"(r[3]) : "r"(addr));
}

__device__ __forceinline__ void mma_bf16(float* d, const unsigned* a, const unsigned* b) {
    asm volatile("mma.sync.aligned.m16n8k16.row.col.f32.bf16.bf16.f32 "
                 "{%0,%1,%2,%3}, {%4,%5,%6,%7}, {%8,%9}, {%0,%1,%2,%3};"
                 : "+f"(d[0]), "+f"(d[1]), "+f"(d[2]), "+f"(d[3])
                 : "r"(a[0]), "r"(a[1]), "r"(a[2]), "r"(a[3]), "r"(b[0]), "r"(b[1]));
}

// stage W chunk c (0..31): pass p = c>>3, k-chunk kc = c&7, into parity buffer c&1.
// Buffer rows padded to 80B; each thread moves 2x16B for hi and lo.
__device__ __forceinline__ void stage_w(char* smem, int c, int tid) {
    int p = c >> 3, kc = c & 7, par = c & 1;
    int rr = tid >> 1, hq = tid & 1;
    size_t src = (size_t)(p * 256 + rr) * HD + kc * 32 + hq * 16;
    char* dst = smem + WBOFF + par * (2 * WBUFSZ) + rr * WROWB + hq * 32;
    cp16(dst,                g_whi + src);
    cp16(dst + 16,           g_whi + src + 8);
    cp16(dst + WBUFSZ,       g_wlo + src);
    cp16(dst + WBUFSZ + 16,  g_wlo + src + 8);
}

// CTA = 64 rows for all 64 steps. 16 warps = 4 row-groups (m16) x 4 col-quads.
// Per pass p (64 h-cols): warp (rg,q) computes 16 rows x 16 h-cols x 4 gates via
// mma.sync m16n8k16 bf16 split-3 (fp32 accum). c-state in regs, h double-buffered
// bf16 hi/lo in smem, W streamed from pre-split globals via cp.async.
__global__ void __launch_bounds__(NTHR, 1)
lstm_decode_kernel(const float* __restrict__ enc,
                   const float* __restrict__ finalx,
                   const float* __restrict__ W_enc,
                   const float* __restrict__ b_enc,
                   const float* __restrict__ W_red,
                   const float* __restrict__ b_red,
                   float* __restrict__ out)
{
    extern __shared__ char smem[];
    float* shv    = (float*)(smem + VOFF);
    float* shu    = (float*)(smem + UOFF);
    float* shwred = (float*)(smem + WREDOFF);
    float* shy    = (float*)(smem + YOFF);
    float* shpart = (float*)(smem + PARTOFF);

    const int tid = threadIdx.x;
    const int w   = tid >> 5;
    const int l   = tid & 31;
    const int rg  = w >> 2;
    const int q   = w & 3;
    const int row0 = blockIdx.x * MROWS;

    for (int i = tid; i < GD; i += NTHR) { shv[i] = g_v[i]; shu[i] = g_u[i]; }
    for (int i = tid; i < HD; i += NTHR) shwred[i] = W_red[i];
    if (tid < MROWS) shy[tid] = finalx[row0 + tid];
    const float bred = __ldg(b_red);

    // ---- h0 = enc @ W_enc + b_enc  ([64,512]@[512,256], scalar fp32) ----
    {
        float* senc = (float*)(smem + WBOFF);            // [64][32]
        float* swe  = (float*)(smem + WBOFF + 8192);     // [32][256]
        float a[4][8];
        #pragma unroll
        for (int r = 0; r < 4; ++r)
            #pragma unroll
            for (int c = 0; c < 8; ++c) a[r][c] = 0.f;

        for (int k0 = 0; k0 < ENCD; k0 += 32) {
            __syncthreads();
            { int r = tid >> 3, c4 = (tid & 7) * 4;
              *(float4*)(senc + r * 32 + c4) =
                  *(const float4*)(enc + (size_t)(row0 + r) * ENCD + k0 + c4); }
            #pragma unroll
            for (int s = 0; s < 4; ++s) {
                int slot = tid + s * NTHR;
                int kk = slot >> 6, c4 = (slot & 63) * 4;
                *(float4*)(swe + kk * 256 + c4) =
                    *(const float4*)(W_enc + (size_t)(k0 + kk) * HD + c4);
            }
            __syncthreads();
            #pragma unroll
            for (int kk = 0; kk < 32; ++kk) {
                float av[4];
                #pragma unroll
                for (int r = 0; r < 4; ++r) av[r] = senc[(4 * w + r) * 32 + kk];
                float4 b0 = *(const float4*)(swe + kk * 256 + l * 8);
                float4 b1 = *(const float4*)(swe + kk * 256 + l * 8 + 4);
                #pragma unroll
                for (int r = 0; r < 4; ++r) {
                    a[r][0] += av[r] * b0.x; a[r][1] += av[r] * b0.y;
                    a[r][2] += av[r] * b0.z; a[r][3] += av[r] * b0.w;
                    a[r][4] += av[r] * b1.x; a[r][5] += av[r] * b1.y;
                    a[r][6] += av[r] * b1.z; a[r][7] += av[r] * b1.w;
                }
            }
        }
        __syncthreads();   // swe reads done before wbuf reuse below
        __nv_bfloat16* hh = (__nv_bfloat16*)(smem);
        __nv_bfloat16* hl = (__nv_bfloat16*)(smem + HBYTES);
        #pragma unroll
        for (int r = 0; r < 4; ++r)
            #pragma unroll
            for (int c = 0; c < 8; ++c) {
                float val = a[r][c] + __ldg(b_enc + l * 8 + c);
                __nv_bfloat16 hi = __float2bfloat16(val);
                hh[(4 * w + r) * HROW + l * 8 + c] = hi;
                hl[(4 * w + r) * HROW + l * 8 + c] =
                    __float2bfloat16(val - __bfloat162float(hi));
            }
    }

    // prologue: stage W chunk 0
    stage_w(smem, 0, tid);
    asm volatile("cp.async.commit_group;");

    const unsigned smem_sh = (unsigned)__cvta_generic_to_shared(smem);
    // A (h) ldmatrix address: row = rg*16 + (l&15), k-half = l>>4
    const unsigned a_off = (rg * 16 + (l & 15)) * HROWB + (l >> 4) * 16;
    // B (W) ldmatrix address within a version buffer: nrow = q*16 + (l&7) + ((l>>4)<<3)
    const unsigned b_off = (q * 16 + (l & 7) + ((l >> 4) << 3)) * WROWB + ((l >> 3) & 1) * 16;
    const int r0 = rg * 16 + (l >> 2);
    const int r1 = r0 + 8;

    float cst[4][2][2][2];
    #pragma unroll
    for (int p = 0; p < 4; ++p)
        #pragma unroll
        for (int j = 0; j < 2; ++j) {
            cst[p][j][0][0] = 0.f; cst[p][j][0][1] = 0.f;
            cst[p][j][1][0] = 0.f; cst[p][j][1][1] = 0.f;
        }

    for (int t = 0; t < TSTEPS; ++t) {
        const unsigned hcur = smem_sh + (unsigned)(t & 1) * (2 * HBYTES);
        const unsigned ahib = hcur + a_off;
        const unsigned alob = hcur + HBYTES + a_off;
        __nv_bfloat16* hn_hi = (__nv_bfloat16*)(smem + ((t + 1) & 1) * (2 * HBYTES));
        __nv_bfloat16* hn_lo = (__nv_bfloat16*)(smem + ((t + 1) & 1) * (2 * HBYTES) + HBYTES);
        float yd0 = 0.f, yd1 = 0.f;

        #pragma unroll
        for (int p = 0; p < 4; ++p) {
            float acc[4][2][4];
            #pragma unroll
            for (int g = 0; g < 4; ++g)
                #pragma unroll
                for (int j = 0; j < 2; ++j) {
                    acc[g][j][0] = 0.f; acc[g][j][1] = 0.f;
                    acc[g][j][2] = 0.f; acc[g][j][3] = 0.f;
                }

            #pragma unroll 1
            for (int kc = 0; kc < 8; ++kc) {
                int c = p * 8 + kc;
                stage_w(smem, (c + 1) & 31, tid);
                asm volatile("cp.async.commit_group;");
                asm volatile("cp.async.wait_group 1;");
                __syncthreads();                         // chunk c visible to all

                unsigned wb = smem_sh + WBOFF + (unsigned)(kc & 1) * (2 * WBUFSZ);
                #pragma unroll
                for (int s = 0; s < 2; ++s) {
                    unsigned ahi[4], alo[4];
                    unsigned ak = (unsigned)(kc * 64 + s * 32);
                    ldm_x4(ahi, ahib + ak);
                    ldm_x4(alo, alob + ak);
                    #pragma unroll
                    for (int g = 0; g < 4; ++g) {
                        unsigned bhi[4], blo[4];
                        unsigned baddr = wb + (unsigned)(g * 64 * WROWB) + b_off + s * 32;
                        ldm_x4(bhi, baddr);
                        ldm_x4(blo, baddr + WBUFSZ);
                        mma_bf16(acc[g][0], ahi, bhi + 0);
                        mma_bf16(acc[g][1], ahi, bhi + 2);
                        mma_bf16(acc[g][0], ahi, blo + 0);
                        mma_bf16(acc[g][1], ahi, blo + 2);
                        mma_bf16(acc[g][0], alo, bhi + 0);
                        mma_bf16(acc[g][1], alo, bhi + 2);
                    }
                }
                __syncthreads();                         // consumption done before restage
            }

            // ---- epilogue for pass p (warp-local gates) ----
            float yp0 = shy[r0], yp1 = shy[r1];
            #pragma unroll
            for (int j = 0; j < 2; ++j)
                #pragma unroll
                for (int cp = 0; cp < 2; ++cp) {
                    int hcol = p * 64 + q * 16 + j * 8 + (l & 3) * 2 + cp;
                    float vi = shv[hcol],          ui = shu[hcol];
                    float vf = shv[HD + hcol],     uf = shu[HD + hcol];
                    float vc = shv[2 * HD + hcol], uc = shu[2 * HD + hcol];
                    float vo = shv[3 * HD + hcol], uo = shu[3 * HD + hcol];
                    float wr = shwred[hcol];
                    #pragma unroll
                    for (int rh = 0; rh < 2; ++rh) {
                        float yy = rh ? yp1 : yp0;
                        int di = rh * 2 + cp;
                        float gi = acc[0][j][di] + yy * vi + ui;
                        float gf = acc[1][j][di] + yy * vf + uf;
                        float gc = acc[2][j][di] + yy * vc + uc;
                        float go = acc[3][j][di] + yy * vo + uo;
                        float cn = sigmoidf_(gf) * cst[p][j][rh][cp]
                                 + sigmoidf_(gi) * tanh_fast(gc);
                        float hn = sigmoidf_(go) * tanh_fast(cn);
                        cst[p][j][rh][cp] = cn;
                        int r = rh ? r1 : r0;
                        __nv_bfloat16 hb = __float2bfloat16(hn);
                        hn_hi[r * HROW + hcol] = hb;
                        hn_lo[r * HROW + hcol] =
                            __float2bfloat16(hn - __bfloat162float(hb));
                        if (rh) yd1 += hn * wr; else yd0 += hn * wr;
                    }
                }
        }

        // ---- y = h_new @ w_red + b_red ----
        yd0 += __shfl_xor_sync(0xffffffffu, yd0, 1);
        yd0 += __shfl_xor_sync(0xffffffffu, yd0, 2);
        yd1 += __shfl_xor_sync(0xffffffffu, yd1, 1);
        yd1 += __shfl_xor_sync(0xffffffffu, yd1, 2);
        if ((l & 3) == 0) {
            shpart[r0 * 4 + q] = yd0;
            shpart[r1 * 4 + q] = yd1;
        }
        __syncthreads();
        if (tid < MROWS) {
            float y = shpart[tid * 4] + shpart[tid * 4 + 1]
                    + shpart[tid * 4 + 2] + shpart[tid * 4 + 3] + bred;
            shy[tid] = y;
            out[(size_t)(row0 + tid) * TSTEPS + t] = y;
        }
        // next step's chunk-0 __syncthreads orders shy/h writes before reads
    }
    asm volatile("cp.async.wait_group 0;");
}

extern "C" void kernel_launch(void* const* d_in, const int* in_sizes, int n_in,
                              void* d_out, int out_size) {
    const float* enc    = (const float*)d_in[0];
    const float* finalx = (const float*)d_in[1];
    const float* W_emb  = (const float*)d_in[2];
    const float* b_emb  = (const float*)d_in[3];
    const float* W_enc  = (const float*)d_in[4];
    const float* b_enc  = (const float*)d_in[5];
    const float* W_k    = (const float*)d_in[6];
    const float* W_r    = (const float*)d_in[7];
    const float* b_lstm = (const float*)d_in[8];
    const float* W_red  = (const float*)d_in[9];
    const float* b_red  = (const float*)d_in[10];
    float* out = (float*)d_out;

    cudaFuncSetAttribute(lstm_decode_kernel,
                         cudaFuncAttributeMaxDynamicSharedMemorySize, SMEMSZ);

    precompute_vu_kernel<<<1, 1024>>>(W_emb, b_emb, W_k, b_lstm);
    precompute_w_kernel<<<512, 512>>>(W_r);
    lstm_decode_kernel<<<BATCH / MROWS, NTHR, SMEMSZ>>>(
        enc, finalx, W_enc, b_enc, W_red, b_red, out);
}